// round 12
// baseline (speedup 1.0000x reference)
#include <cuda_runtime.h>
#include <cuda_bf16.h>
#include <math.h>
#include <stdint.h>

#define S_LEN   2048
#define DMODEL  1024
#define NHEADS  16
#define HDIM    64
#define BATCH   2
#define MROWS   (BATCH * S_LEN)   // 4096

extern __shared__ __align__(128) float dyn_smem[];

// ---------------------------------------------------------------------------
// Global scratch
// ---------------------------------------------------------------------------
__device__ __align__(128) __nv_bfloat16 g_Xhi[MROWS * DMODEL];
__device__ __align__(128) __nv_bfloat16 g_Xlo[MROWS * DMODEL];
__device__ __align__(128) __nv_bfloat16 g_Wthi[3 * DMODEL * DMODEL];
__device__ __align__(128) __nv_bfloat16 g_Wtlo[3 * DMODEL * DMODEL];
__device__ __align__(128) __nv_bfloat16 g_Wohi[DMODEL * DMODEL];
__device__ __align__(128) __nv_bfloat16 g_Wolo[DMODEL * DMODEL];
__device__ __align__(128) __nv_bfloat16 g_Chi[MROWS * DMODEL];
__device__ __align__(128) __nv_bfloat16 g_Clo[MROWS * DMODEL];
__device__ __align__(128) __nv_bfloat16 g_QKVhi[3 * MROWS * DMODEL];  // Q scaled by 0.125*log2e
__device__ __align__(128) __nv_bfloat16 g_QKVlo[3 * MROWS * DMODEL];

// ---------------------------------------------------------------------------
// Helpers
// ---------------------------------------------------------------------------
__device__ __forceinline__ uint32_t smem_u32(const void* p) {
    uint32_t a;
    asm("{ .reg .u64 t; cvta.to.shared.u64 t, %1; cvt.u32.u64 %0, t; }" : "=r"(a) : "l"(p));
    return a;
}
__device__ __forceinline__ void ldsm_x4(uint32_t* r, uint32_t addr) {
    asm volatile("ldmatrix.sync.aligned.m8n8.x4.shared.b16 {%0,%1,%2,%3}, [%4];"
                 : "=r"(r[0]), "=r"(r[1]), "=r"(r[2]), "=r"(r[3]) : "r"(addr));
}
__device__ __forceinline__ void ldsm_x4_t(uint32_t* r, uint32_t addr) {
    asm volatile("ldmatrix.sync.aligned.m8n8.x4.trans.shared.b16 {%0,%1,%2,%3}, [%4];"
                 : "=r"(r[0]), "=r"(r[1]), "=r"(r[2]), "=r"(r[3]) : "r"(addr));
}
__device__ __forceinline__ void mma_bf16(float* c, const uint32_t* a, uint32_t b0, uint32_t b1) {
    asm volatile(
        "mma.sync.aligned.m16n8k16.row.col.f32.bf16.bf16.f32 "
        "{%0,%1,%2,%3},{%4,%5,%6,%7},{%8,%9},{%0,%1,%2,%3};"
        : "+f"(c[0]), "+f"(c[1]), "+f"(c[2]), "+f"(c[3])
        : "r"(a[0]), "r"(a[1]), "r"(a[2]), "r"(a[3]), "r"(b0), "r"(b1));
}
__device__ __forceinline__ float ex2f(float x) {
    float r;
    asm("ex2.approx.f32 %0, %1;" : "=f"(r) : "f"(x));
    return r;
}
// split-pack: out_hi/out_lo get bf16 hi/lo pairs of (a,b)
__device__ __forceinline__ void split_pack(float a, float b, uint32_t& oh, uint32_t& ol) {
    __nv_bfloat16 ha = __float2bfloat16(a), hb = __float2bfloat16(b);
    float la = a - __bfloat162float(ha), lb = b - __bfloat162float(hb);
    __nv_bfloat162 th, tl;
    th.x = ha; th.y = hb;
    tl.x = __float2bfloat16(la); tl.y = __float2bfloat16(lb);
    oh = *(uint32_t*)&th; ol = *(uint32_t*)&tl;
}
__device__ __forceinline__ uint32_t sw128(uint32_t off) {
    return off ^ ((off >> 3) & 0x70);
}

// ---------------------------------------------------------------------------
// Pre-pass splits
// ---------------------------------------------------------------------------
__global__ void split_kernel(const float* __restrict__ src, int n, int mode) {
    __nv_bfloat16* hi = mode ? g_Wohi : g_Xhi;
    __nv_bfloat16* lo = mode ? g_Wolo : g_Xlo;
    int i = blockIdx.x * 256 + threadIdx.x;
    if (i < n) {
        float a = src[i];
        __nv_bfloat16 h = __float2bfloat16(a);
        hi[i] = h;
        lo[i] = __float2bfloat16(a - __bfloat162float(h));
    }
}

__global__ void tsplit_kernel(const float* __restrict__ Wq,
                              const float* __restrict__ Wk,
                              const float* __restrict__ Wv) {
    const float* W = (blockIdx.z == 0) ? Wq : (blockIdx.z == 1) ? Wk : Wv;
    __nv_bfloat16* Hi = g_Wthi + (size_t)blockIdx.z * DMODEL * DMODEL;
    __nv_bfloat16* Lo = g_Wtlo + (size_t)blockIdx.z * DMODEL * DMODEL;
    __shared__ float t[32][33];
    const int k0 = blockIdx.y * 32, n0 = blockIdx.x * 32;
    const int tx = threadIdx.x, ty = threadIdx.y;
#pragma unroll
    for (int r = 0; r < 4; r++)
        t[ty + 8 * r][tx] = W[(size_t)(k0 + ty + 8 * r) * DMODEL + n0 + tx];
    __syncthreads();
#pragma unroll
    for (int r = 0; r < 4; r++) {
        float a = t[tx][ty + 8 * r];
        size_t idx = (size_t)(n0 + ty + 8 * r) * DMODEL + k0 + tx;
        __nv_bfloat16 h = __float2bfloat16(a);
        Hi[idx] = h;
        Lo[idx] = __float2bfloat16(a - __bfloat162float(h));
    }
}

// ---------------------------------------------------------------------------
// Tile loaders
// ---------------------------------------------------------------------------
__device__ __forceinline__ void at_load64(uint32_t sdst, const __nv_bfloat16* g, int tid) {
#pragma unroll
    for (int t = 0; t < 2; t++) {
        int cid = t * 256 + tid;
        int r = cid >> 3, ch = cid & 7;
        uint32_t off = sw128((uint32_t)(r * 128 + ch * 16));
        const char* src = (const char*)(g + (size_t)r * DMODEL) + ch * 16;
        asm volatile("cp.async.cg.shared.global [%0], [%1], 16;" :: "r"(sdst + off), "l"(src));
    }
}
__device__ __forceinline__ void at_load128(uint32_t sdst, const __nv_bfloat16* g, int tid) {
#pragma unroll
    for (int t = 0; t < 4; t++) {
        int cid = t * 256 + tid;
        int r = cid >> 3, ch = cid & 7;
        uint32_t off = sw128((uint32_t)(r * 128 + ch * 16));
        const char* src = (const char*)(g + (size_t)r * DMODEL) + ch * 16;
        asm volatile("cp.async.cg.shared.global [%0], [%1], 16;" :: "r"(sdst + off), "l"(src));
    }
}

// ---------------------------------------------------------------------------
// bf16 3x mma GEMM (unchanged from R11), 128x64 CTA tile, 2 CTAs/SM.
// ---------------------------------------------------------------------------
#define GS_STAGE 49152
#define GS_AHI   0
#define GS_ALO   16384
#define GS_BHI   32768
#define GS_BLO   40960
#define GS_TOTAL (2 * GS_STAGE)   // 98304

__global__ __launch_bounds__(256, 2) void gemm_kernel(int mode, float* __restrict__ outp,
                                                      const float* __restrict__ biasp) {
    uint32_t sb = smem_u32(dyn_smem);
    const int tid = threadIdx.x, lane = tid & 31, wid = tid >> 5;
    const int wm = (wid >> 1) * 32;
    const int wn = (wid & 1) * 32;
    const int rowBase = blockIdx.y * 128;
    const int colBase = blockIdx.x * 64;
    const int z = blockIdx.z;
    const int rA = lane & 15, cb16 = (lane >> 4) << 4;

    const __nv_bfloat16 *Ah, *Al, *Bh, *Bl;
    if (mode == 0) {
        Ah = g_Xhi; Al = g_Xlo;
        Bh = g_Wthi + (size_t)z * DMODEL * DMODEL;
        Bl = g_Wtlo + (size_t)z * DMODEL * DMODEL;
    } else {
        Ah = g_Chi; Al = g_Clo;
        Bh = g_Wohi; Bl = g_Wolo;
    }
    Ah += (size_t)rowBase * DMODEL;
    Al += (size_t)rowBase * DMODEL;
    Bh += (size_t)colBase * DMODEL;
    Bl += (size_t)colBase * DMODEL;

    uint32_t aOff[2][4], bOff[2][4];
#pragma unroll
    for (int mt = 0; mt < 2; mt++)
#pragma unroll
        for (int ks = 0; ks < 4; ks++)
            aOff[mt][ks] = sw128((uint32_t)((wm + mt * 16 + rA) * 128 + ks * 32 + cb16));
#pragma unroll
    for (int nt = 0; nt < 2; nt++)
#pragma unroll
        for (int ks = 0; ks < 4; ks++)
            bOff[nt][ks] = sw128((uint32_t)((wn + nt * 16 + rA) * 128 + ks * 32 + cb16));

    float c[2][4][4];
#pragma unroll
    for (int i = 0; i < 2; i++)
#pragma unroll
        for (int j = 0; j < 4; j++)
#pragma unroll
            for (int k = 0; k < 4; k++) c[i][j][k] = 0.f;

    at_load128(sb + GS_AHI, Ah, tid);
    at_load128(sb + GS_ALO, Al, tid);
    at_load64(sb + GS_BHI, Bh, tid);
    at_load64(sb + GS_BLO, Bl, tid);
    asm volatile("cp.async.commit_group;");

    for (int ck = 0; ck < 16; ck++) {
        const int s = ck & 1;
        asm volatile("cp.async.wait_group 0;");
        __syncthreads();

        const uint32_t aHi = sb + (uint32_t)s * GS_STAGE + GS_AHI;
        const uint32_t aLo = sb + (uint32_t)s * GS_STAGE + GS_ALO;
        const uint32_t bHi = sb + (uint32_t)s * GS_STAGE + GS_BHI;
        const uint32_t bLo = sb + (uint32_t)s * GS_STAGE + GS_BLO;

#pragma unroll
        for (int ks = 0; ks < 4; ks++) {
            uint32_t AhF[2][4], AlF[2][4], BhF[2][4], BlF[2][4];
#pragma unroll
            for (int mt = 0; mt < 2; mt++) {
                ldsm_x4(AhF[mt], aHi + aOff[mt][ks]);
                ldsm_x4(AlF[mt], aLo + aOff[mt][ks]);
            }
#pragma unroll
            for (int nt = 0; nt < 2; nt++) {
                ldsm_x4(BhF[nt], bHi + bOff[nt][ks]);
                ldsm_x4(BlF[nt], bLo + bOff[nt][ks]);
            }
#pragma unroll
            for (int mt = 0; mt < 2; mt++) {
#pragma unroll
                for (int nt = 0; nt < 2; nt++) {
#pragma unroll
                    for (int o = 0; o < 2; o++) {
                        mma_bf16(c[mt][nt * 2 + o], AhF[mt], BhF[nt][o], BhF[nt][o + 2]);
                        mma_bf16(c[mt][nt * 2 + o], AhF[mt], BlF[nt][o], BlF[nt][o + 2]);
                        mma_bf16(c[mt][nt * 2 + o], AlF[mt], BhF[nt][o], BhF[nt][o + 2]);
                    }
                }
            }
            if (ks == 0 && ck + 1 < 16) {
                uint32_t st = sb + (uint32_t)((ck + 1) & 1) * GS_STAGE;
                const int k0 = (ck + 1) * 64;
                at_load128(st + GS_AHI, Ah + k0, tid);
                at_load128(st + GS_ALO, Al + k0, tid);
                at_load64(st + GS_BHI, Bh + k0, tid);
                at_load64(st + GS_BLO, Bl + k0, tid);
                asm volatile("cp.async.commit_group;");
            }
        }
    }

    const int cl = 2 * (lane & 3);
    if (mode == 0) {
        const float scale = (z == 0) ? 0.125f * 1.4426950408889634f : 1.0f;
        __nv_bfloat16* Hi = g_QKVhi + (size_t)z * MROWS * DMODEL;
        __nv_bfloat16* Lo = g_QKVlo + (size_t)z * MROWS * DMODEL;
#pragma unroll
        for (int mt = 0; mt < 2; mt++) {
            const int r0 = rowBase + wm + mt * 16 + (lane >> 2);
#pragma unroll
            for (int nf = 0; nf < 4; nf++) {
                const int col = colBase + wn + nf * 8 + cl;
                uint32_t h0, l0, h1, l1;
                split_pack(c[mt][nf][0] * scale, c[mt][nf][1] * scale, h0, l0);
                split_pack(c[mt][nf][2] * scale, c[mt][nf][3] * scale, h1, l1);
                *(uint32_t*)&Hi[(size_t)r0 * DMODEL + col] = h0;
                *(uint32_t*)&Lo[(size_t)r0 * DMODEL + col] = l0;
                *(uint32_t*)&Hi[(size_t)(r0 + 8) * DMODEL + col] = h1;
                *(uint32_t*)&Lo[(size_t)(r0 + 8) * DMODEL + col] = l1;
            }
        }
    } else {
#pragma unroll
        for (int mt = 0; mt < 2; mt++) {
            const int r0 = rowBase + wm + mt * 16 + (lane >> 2);
#pragma unroll
            for (int nf = 0; nf < 4; nf++) {
                const int col = colBase + wn + nf * 8 + cl;
                const float b0 = biasp[col], b1 = biasp[col + 1];
                float2 v0 = make_float2(c[mt][nf][0] + b0, c[mt][nf][1] + b1);
                float2 v1 = make_float2(c[mt][nf][2] + b0, c[mt][nf][3] + b1);
                *(float2*)&outp[(size_t)r0 * DMODEL + col] = v0;
                *(float2*)&outp[(size_t)(r0 + 8) * DMODEL + col] = v1;
            }
        }
    }
}

// ---------------------------------------------------------------------------
// Tensor-core causal flash attention; exp2 softmax; 2 CTAs/SM.
// Q fragments re-loaded from smem per tile (reg pressure < 128).
// ---------------------------------------------------------------------------
#define AT_STAGE 32768
#define AT_KHI   0
#define AT_KLO   8192
#define AT_VHI   16384
#define AT_VLO   24576
#define AT_QHI   65536
#define AT_QLO   81920
#define AT_TOTAL 98304

__global__ __launch_bounds__(256, 2) void attn_kernel() {
    uint32_t sb = smem_u32(dyn_smem);
    const int tid = threadIdx.x, lane = tid & 31, wid = tid >> 5;
    const int qt = gridDim.x - 1 - blockIdx.x;   // heavy CTAs first
    const int bh = blockIdx.y;
    const int b = bh >> 4, h = bh & 15;
    const int wm = wid * 16;
    const int rA = lane & 15, cb16 = (lane >> 4) << 4;
    const int jmax = 2 * qt + 1;

    const size_t qoff = ((size_t)b * S_LEN + qt * 128) * DMODEL + h * HDIM;
    const __nv_bfloat16* Qh_g = g_QKVhi + qoff;
    const __nv_bfloat16* Ql_g = g_QKVlo + qoff;
    const size_t kvbase = (size_t)b * S_LEN * DMODEL + h * HDIM;
    const __nv_bfloat16* Kh_g = g_QKVhi + (size_t)MROWS * DMODEL + kvbase;
    const __nv_bfloat16* Kl_g = g_QKVlo + (size_t)MROWS * DMODEL + kvbase;
    const __nv_bfloat16* Vh_g = g_QKVhi + (size_t)2 * MROWS * DMODEL + kvbase;
    const __nv_bfloat16* Vl_g = g_QKVlo + (size_t)2 * MROWS * DMODEL + kvbase;

    at_load128(sb + AT_QHI, Qh_g, tid);
    at_load128(sb + AT_QLO, Ql_g, tid);
    at_load64(sb + AT_KHI, Kh_g, tid);
    at_load64(sb + AT_KLO, Kl_g, tid);
    at_load64(sb + AT_VHI, Vh_g, tid);
    at_load64(sb + AT_VLO, Vl_g, tid);
    asm volatile("cp.async.commit_group;");

    float co[8][4];
#pragma unroll
    for (int i = 0; i < 8; i++)
#pragma unroll
        for (int j = 0; j < 4; j++) co[i][j] = 0.f;
    float m_i[2] = {-INFINITY, -INFINITY};
    float l_i[2] = {0.f, 0.f};

    for (int j = 0; j <= jmax; j++) {
        asm volatile("cp.async.wait_group 0;");
        __syncthreads();

        if (j + 1 <= jmax) {
            uint32_t stn = sb + (uint32_t)((j + 1) & 1) * AT_STAGE;
            const size_t ro = (size_t)(j + 1) * 64 * DMODEL;
            at_load64(stn + AT_KHI, Kh_g + ro, tid);
            at_load64(stn + AT_KLO, Kl_g + ro, tid);
            at_load64(stn + AT_VHI, Vh_g + ro, tid);
            at_load64(stn + AT_VLO, Vl_g + ro, tid);
            asm volatile("cp.async.commit_group;");
        }

        const int qmin = qt * 128 + wm;
        if (j * 64 > qmin + 15) continue;

        const uint32_t st = sb + (uint32_t)(j & 1) * AT_STAGE;

        // ---- S = Q K^T (Q fragments re-loaded from stable smem) ----
        float cs[8][4];
#pragma unroll
        for (int i = 0; i < 8; i++)
#pragma unroll
            for (int e = 0; e < 4; e++) cs[i][e] = 0.f;
#pragma unroll
        for (int ks = 0; ks < 4; ks++) {
            uint32_t qh[4], ql[4];
            uint32_t qo = sw128((uint32_t)((wm + rA) * 128 + ks * 32 + cb16));
            ldsm_x4(qh, sb + AT_QHI + qo);
            ldsm_x4(ql, sb + AT_QLO + qo);
#pragma unroll
            for (int nt = 0; nt < 4; nt++) {
                uint32_t kh[4], kl[4];
                uint32_t off = sw128((uint32_t)((nt * 16 + rA) * 128 + ks * 32 + cb16));
                ldsm_x4(kh, st + AT_KHI + off);
                ldsm_x4(kl, st + AT_KLO + off);
#pragma unroll
                for (int o = 0; o < 2; o++) {
                    mma_bf16(cs[nt * 2 + o], qh, kh[o], kh[o + 2]);
                    mma_bf16(cs[nt * 2 + o], qh, kl[o], kl[o + 2]);
                    mma_bf16(cs[nt * 2 + o], ql, kh[o], kh[o + 2]);
                }
            }
        }

        if (j * 64 + 63 > qmin) {
            const int r0 = lane >> 2, c0 = 2 * (lane & 3);
#pragma unroll
            for (int nf = 0; nf < 8; nf++) {
#pragma unroll
                for (int e = 0; e < 4; e++) {
                    const int col = nf * 8 + c0 + (e & 1);
                    const int row = r0 + ((e >> 1) * 8);
                    if (j * 64 + col > qmin + row) cs[nf][e] = -1e30f;
                }
            }
        }

        // ---- online softmax (exp2 domain) ----
        float mx0 = -INFINITY, mx1 = -INFINITY;
#pragma unroll
        for (int nf = 0; nf < 8; nf++) {
            mx0 = fmaxf(mx0, fmaxf(cs[nf][0], cs[nf][1]));
            mx1 = fmaxf(mx1, fmaxf(cs[nf][2], cs[nf][3]));
        }
        mx0 = fmaxf(mx0, __shfl_xor_sync(0xffffffffu, mx0, 1));
        mx0 = fmaxf(mx0, __shfl_xor_sync(0xffffffffu, mx0, 2));
        mx1 = fmaxf(mx1, __shfl_xor_sync(0xffffffffu, mx1, 1));
        mx1 = fmaxf(mx1, __shfl_xor_sync(0xffffffffu, mx1, 2));
        const float mn0 = fmaxf(m_i[0], mx0), mn1 = fmaxf(m_i[1], mx1);
        const float corr0 = ex2f(m_i[0] - mn0), corr1 = ex2f(m_i[1] - mn1);
        float rs0 = 0.f, rs1 = 0.f;
#pragma unroll
        for (int nf = 0; nf < 8; nf++) {
            cs[nf][0] = ex2f(cs[nf][0] - mn0); rs0 += cs[nf][0];
            cs[nf][1] = ex2f(cs[nf][1] - mn0); rs0 += cs[nf][1];
            cs[nf][2] = ex2f(cs[nf][2] - mn1); rs1 += cs[nf][2];
            cs[nf][3] = ex2f(cs[nf][3] - mn1); rs1 += cs[nf][3];
        }
        rs0 += __shfl_xor_sync(0xffffffffu, rs0, 1);
        rs0 += __shfl_xor_sync(0xffffffffu, rs0, 2);
        rs1 += __shfl_xor_sync(0xffffffffu, rs1, 1);
        rs1 += __shfl_xor_sync(0xffffffffu, rs1, 2);
        l_i[0] = l_i[0] * corr0 + rs0; m_i[0] = mn0;
        l_i[1] = l_i[1] * corr1 + rs1; m_i[1] = mn1;
#pragma unroll
        for (int nf = 0; nf < 8; nf++) {
            co[nf][0] *= corr0; co[nf][1] *= corr0;
            co[nf][2] *= corr1; co[nf][3] *= corr1;
        }

        // ---- O += P V ----
#pragma unroll
        for (int kt = 0; kt < 4; kt++) {
            uint32_t pah[4], pal[4];
            split_pack(cs[2 * kt][0],     cs[2 * kt][1],     pah[0], pal[0]);
            split_pack(cs[2 * kt][2],     cs[2 * kt][3],     pah[1], pal[1]);
            split_pack(cs[2 * kt + 1][0], cs[2 * kt + 1][1], pah[2], pal[2]);
            split_pack(cs[2 * kt + 1][2], cs[2 * kt + 1][3], pah[3], pal[3]);
#pragma unroll
            for (int nt = 0; nt < 4; nt++) {
                uint32_t vh[4], vl[4];
                uint32_t off = sw128((uint32_t)((kt * 16 + rA) * 128 + nt * 32 + cb16));
                ldsm_x4_t(vh, st + AT_VHI + off);
                ldsm_x4_t(vl, st + AT_VLO + off);
                mma_bf16(co[nt * 2 + 0], pah, vh[0], vh[1]);
                mma_bf16(co[nt * 2 + 0], pah, vl[0], vl[1]);
                mma_bf16(co[nt * 2 + 0], pal, vh[0], vh[1]);
                mma_bf16(co[nt * 2 + 1], pah, vh[2], vh[3]);
                mma_bf16(co[nt * 2 + 1], pah, vl[2], vl[3]);
                mma_bf16(co[nt * 2 + 1], pal, vh[2], vh[3]);
            }
        }
    }

    const float inv0 = 1.f / l_i[0], inv1 = 1.f / l_i[1];
    const int row0 = b * S_LEN + qt * 128 + wm + (lane >> 2);
    const int colb = h * HDIM + 2 * (lane & 3);
#pragma unroll
    for (int nf = 0; nf < 8; nf++) {
        const int col = colb + nf * 8;
        uint32_t h0, l0, h1, l1;
        split_pack(co[nf][0] * inv0, co[nf][1] * inv0, h0, l0);
        split_pack(co[nf][2] * inv1, co[nf][3] * inv1, h1, l1);
        *(uint32_t*)&g_Chi[(size_t)row0 * DMODEL + col] = h0;
        *(uint32_t*)&g_Clo[(size_t)row0 * DMODEL + col] = l0;
        *(uint32_t*)&g_Chi[(size_t)(row0 + 8) * DMODEL + col] = h1;
        *(uint32_t*)&g_Clo[(size_t)(row0 + 8) * DMODEL + col] = l1;
    }
}

// ---------------------------------------------------------------------------
extern "C" void kernel_launch(void* const* d_in, const int* in_sizes, int n_in,
                              void* d_out, int out_size)
{
    const float* x  = (const float*)d_in[0];
    const float* Wq = (const float*)d_in[1];
    const float* Wk = (const float*)d_in[2];
    const float* Wv = (const float*)d_in[3];
    const float* Wo = (const float*)d_in[4];
    const float* bo = (const float*)d_in[5];
    float* out = (float*)d_out;

    cudaFuncSetAttribute(gemm_kernel, cudaFuncAttributeMaxDynamicSharedMemorySize, GS_TOTAL);
    cudaFuncSetAttribute(attn_kernel, cudaFuncAttributeMaxDynamicSharedMemorySize, AT_TOTAL);

    split_kernel<<<(MROWS * DMODEL + 255) / 256, 256>>>(x, MROWS * DMODEL, 0);
    split_kernel<<<(DMODEL * DMODEL + 255) / 256, 256>>>(Wo, DMODEL * DMODEL, 1);
    tsplit_kernel<<<dim3(32, 32, 3), dim3(32, 8)>>>(Wq, Wk, Wv);

    gemm_kernel<<<dim3(DMODEL / 64, MROWS / 128, 3), 256, GS_TOTAL>>>(0, nullptr, nullptr);

    attn_kernel<<<dim3(S_LEN / 128, BATCH * NHEADS), 256, AT_TOTAL>>>();

    gemm_kernel<<<dim3(DMODEL / 64, MROWS / 128, 1), 256, GS_TOTAL>>>(1, out, bo);
}

// round 13
// speedup vs baseline: 1.0227x; 1.0227x over previous
#include <cuda_runtime.h>
#include <cuda_bf16.h>
#include <math.h>
#include <stdint.h>

#define S_LEN   2048
#define DMODEL  1024
#define NHEADS  16
#define HDIM    64
#define BATCH   2
#define MROWS   (BATCH * S_LEN)   // 4096

extern __shared__ __align__(128) float dyn_smem[];

// ---------------------------------------------------------------------------
// Global scratch
// ---------------------------------------------------------------------------
__device__ __align__(128) __nv_bfloat16 g_Xhi[MROWS * DMODEL];
__device__ __align__(128) __nv_bfloat16 g_Xlo[MROWS * DMODEL];
__device__ __align__(128) __nv_bfloat16 g_Wthi[3 * DMODEL * DMODEL];
__device__ __align__(128) __nv_bfloat16 g_Wtlo[3 * DMODEL * DMODEL];
__device__ __align__(128) __nv_bfloat16 g_Wohi[DMODEL * DMODEL];
__device__ __align__(128) __nv_bfloat16 g_Wolo[DMODEL * DMODEL];
__device__ __align__(128) __nv_bfloat16 g_Chi[MROWS * DMODEL];
__device__ __align__(128) __nv_bfloat16 g_Clo[MROWS * DMODEL];
__device__ __align__(128) __nv_bfloat16 g_QKVhi[3 * MROWS * DMODEL];  // Q scaled by 0.125*log2e
__device__ __align__(128) __nv_bfloat16 g_QKVlo[3 * MROWS * DMODEL];

// ---------------------------------------------------------------------------
// Helpers
// ---------------------------------------------------------------------------
__device__ __forceinline__ uint32_t smem_u32(const void* p) {
    uint32_t a;
    asm("{ .reg .u64 t; cvta.to.shared.u64 t, %1; cvt.u32.u64 %0, t; }" : "=r"(a) : "l"(p));
    return a;
}
__device__ __forceinline__ void ldsm_x4(uint32_t* r, uint32_t addr) {
    asm volatile("ldmatrix.sync.aligned.m8n8.x4.shared.b16 {%0,%1,%2,%3}, [%4];"
                 : "=r"(r[0]), "=r"(r[1]), "=r"(r[2]), "=r"(r[3]) : "r"(addr));
}
__device__ __forceinline__ void ldsm_x4_t(uint32_t* r, uint32_t addr) {
    asm volatile("ldmatrix.sync.aligned.m8n8.x4.trans.shared.b16 {%0,%1,%2,%3}, [%4];"
                 : "=r"(r[0]), "=r"(r[1]), "=r"(r[2]), "=r"(r[3]) : "r"(addr));
}
__device__ __forceinline__ void mma_bf16(float* c, const uint32_t* a, uint32_t b0, uint32_t b1) {
    asm volatile(
        "mma.sync.aligned.m16n8k16.row.col.f32.bf16.bf16.f32 "
        "{%0,%1,%2,%3},{%4,%5,%6,%7},{%8,%9},{%0,%1,%2,%3};"
        : "+f"(c[0]), "+f"(c[1]), "+f"(c[2]), "+f"(c[3])
        : "r"(a[0]), "r"(a[1]), "r"(a[2]), "r"(a[3]), "r"(b0), "r"(b1));
}
__device__ __forceinline__ float ex2f(float x) {
    float r;
    asm("ex2.approx.f32 %0, %1;" : "=f"(r) : "f"(x));
    return r;
}
// split-pack: out_hi/out_lo get bf16 hi/lo pairs of (a,b)
__device__ __forceinline__ void split_pack(float a, float b, uint32_t& oh, uint32_t& ol) {
    __nv_bfloat16 ha = __float2bfloat16(a), hb = __float2bfloat16(b);
    float la = a - __bfloat162float(ha), lb = b - __bfloat162float(hb);
    __nv_bfloat162 th, tl;
    th.x = ha; th.y = hb;
    tl.x = __float2bfloat16(la); tl.y = __float2bfloat16(lb);
    oh = *(uint32_t*)&th; ol = *(uint32_t*)&tl;
}
__device__ __forceinline__ uint32_t sw128(uint32_t off) {
    return off ^ ((off >> 3) & 0x70);
}

// ---------------------------------------------------------------------------
// Pre-pass splits
// ---------------------------------------------------------------------------
__global__ void split_kernel(const float* __restrict__ src, int n, int mode) {
    __nv_bfloat16* hi = mode ? g_Wohi : g_Xhi;
    __nv_bfloat16* lo = mode ? g_Wolo : g_Xlo;
    int i = blockIdx.x * 256 + threadIdx.x;
    if (i < n) {
        float a = src[i];
        __nv_bfloat16 h = __float2bfloat16(a);
        hi[i] = h;
        lo[i] = __float2bfloat16(a - __bfloat162float(h));
    }
}

__global__ void tsplit_kernel(const float* __restrict__ Wq,
                              const float* __restrict__ Wk,
                              const float* __restrict__ Wv) {
    const float* W = (blockIdx.z == 0) ? Wq : (blockIdx.z == 1) ? Wk : Wv;
    __nv_bfloat16* Hi = g_Wthi + (size_t)blockIdx.z * DMODEL * DMODEL;
    __nv_bfloat16* Lo = g_Wtlo + (size_t)blockIdx.z * DMODEL * DMODEL;
    __shared__ float t[32][33];
    const int k0 = blockIdx.y * 32, n0 = blockIdx.x * 32;
    const int tx = threadIdx.x, ty = threadIdx.y;
#pragma unroll
    for (int r = 0; r < 4; r++)
        t[ty + 8 * r][tx] = W[(size_t)(k0 + ty + 8 * r) * DMODEL + n0 + tx];
    __syncthreads();
#pragma unroll
    for (int r = 0; r < 4; r++) {
        float a = t[tx][ty + 8 * r];
        size_t idx = (size_t)(n0 + ty + 8 * r) * DMODEL + k0 + tx;
        __nv_bfloat16 h = __float2bfloat16(a);
        Hi[idx] = h;
        Lo[idx] = __float2bfloat16(a - __bfloat162float(h));
    }
}

// ---------------------------------------------------------------------------
// Tile loaders
// ---------------------------------------------------------------------------
__device__ __forceinline__ void at_load64(uint32_t sdst, const __nv_bfloat16* g, int tid) {
#pragma unroll
    for (int t = 0; t < 2; t++) {
        int cid = t * 256 + tid;
        int r = cid >> 3, ch = cid & 7;
        uint32_t off = sw128((uint32_t)(r * 128 + ch * 16));
        const char* src = (const char*)(g + (size_t)r * DMODEL) + ch * 16;
        asm volatile("cp.async.cg.shared.global [%0], [%1], 16;" :: "r"(sdst + off), "l"(src));
    }
}
__device__ __forceinline__ void at_load128(uint32_t sdst, const __nv_bfloat16* g, int tid) {
#pragma unroll
    for (int t = 0; t < 4; t++) {
        int cid = t * 256 + tid;
        int r = cid >> 3, ch = cid & 7;
        uint32_t off = sw128((uint32_t)(r * 128 + ch * 16));
        const char* src = (const char*)(g + (size_t)r * DMODEL) + ch * 16;
        asm volatile("cp.async.cg.shared.global [%0], [%1], 16;" :: "r"(sdst + off), "l"(src));
    }
}

// ---------------------------------------------------------------------------
// bf16 3x mma GEMM, 128x64 CTA tile, 2 CTAs/SM.
// Term-major mma ordering: consecutive HMMAs never share an accumulator.
// ---------------------------------------------------------------------------
#define GS_STAGE 49152
#define GS_AHI   0
#define GS_ALO   16384
#define GS_BHI   32768
#define GS_BLO   40960
#define GS_TOTAL (2 * GS_STAGE)   // 98304

__global__ __launch_bounds__(256, 2) void gemm_kernel(int mode, float* __restrict__ outp,
                                                      const float* __restrict__ biasp) {
    uint32_t sb = smem_u32(dyn_smem);
    const int tid = threadIdx.x, lane = tid & 31, wid = tid >> 5;
    const int wm = (wid >> 1) * 32;
    const int wn = (wid & 1) * 32;
    const int rowBase = blockIdx.y * 128;
    const int colBase = blockIdx.x * 64;
    const int z = blockIdx.z;
    const int rA = lane & 15, cb16 = (lane >> 4) << 4;

    const __nv_bfloat16 *Ah, *Al, *Bh, *Bl;
    if (mode == 0) {
        Ah = g_Xhi; Al = g_Xlo;
        Bh = g_Wthi + (size_t)z * DMODEL * DMODEL;
        Bl = g_Wtlo + (size_t)z * DMODEL * DMODEL;
    } else {
        Ah = g_Chi; Al = g_Clo;
        Bh = g_Wohi; Bl = g_Wolo;
    }
    Ah += (size_t)rowBase * DMODEL;
    Al += (size_t)rowBase * DMODEL;
    Bh += (size_t)colBase * DMODEL;
    Bl += (size_t)colBase * DMODEL;

    uint32_t aOff[2][4], bOff[2][4];
#pragma unroll
    for (int mt = 0; mt < 2; mt++)
#pragma unroll
        for (int ks = 0; ks < 4; ks++)
            aOff[mt][ks] = sw128((uint32_t)((wm + mt * 16 + rA) * 128 + ks * 32 + cb16));
#pragma unroll
    for (int nt = 0; nt < 2; nt++)
#pragma unroll
        for (int ks = 0; ks < 4; ks++)
            bOff[nt][ks] = sw128((uint32_t)((wn + nt * 16 + rA) * 128 + ks * 32 + cb16));

    float c[2][4][4];
#pragma unroll
    for (int i = 0; i < 2; i++)
#pragma unroll
        for (int j = 0; j < 4; j++)
#pragma unroll
            for (int k = 0; k < 4; k++) c[i][j][k] = 0.f;

    at_load128(sb + GS_AHI, Ah, tid);
    at_load128(sb + GS_ALO, Al, tid);
    at_load64(sb + GS_BHI, Bh, tid);
    at_load64(sb + GS_BLO, Bl, tid);
    asm volatile("cp.async.commit_group;");

    for (int ck = 0; ck < 16; ck++) {
        const int s = ck & 1;
        asm volatile("cp.async.wait_group 0;");
        __syncthreads();

        const uint32_t aHi = sb + (uint32_t)s * GS_STAGE + GS_AHI;
        const uint32_t aLo = sb + (uint32_t)s * GS_STAGE + GS_ALO;
        const uint32_t bHi = sb + (uint32_t)s * GS_STAGE + GS_BHI;
        const uint32_t bLo = sb + (uint32_t)s * GS_STAGE + GS_BLO;

#pragma unroll
        for (int ks = 0; ks < 4; ks++) {
            uint32_t AhF[2][4], AlF[2][4], BhF[2][4], BlF[2][4];
#pragma unroll
            for (int mt = 0; mt < 2; mt++) {
                ldsm_x4(AhF[mt], aHi + aOff[mt][ks]);
                ldsm_x4(AlF[mt], aLo + aOff[mt][ks]);
            }
#pragma unroll
            for (int nt = 0; nt < 2; nt++) {
                ldsm_x4(BhF[nt], bHi + bOff[nt][ks]);
                ldsm_x4(BlF[nt], bLo + bOff[nt][ks]);
            }
            // term-major: 8 independent accumulators per pass, no back-to-back
            // same-accumulator HMMAs. Per-accumulator order stays hh->hl->lh
            // (bit-identical to previous rounds).
#pragma unroll
            for (int mt = 0; mt < 2; mt++)
#pragma unroll
                for (int nt = 0; nt < 2; nt++)
#pragma unroll
                    for (int o = 0; o < 2; o++)
                        mma_bf16(c[mt][nt * 2 + o], AhF[mt], BhF[nt][o], BhF[nt][o + 2]);
#pragma unroll
            for (int mt = 0; mt < 2; mt++)
#pragma unroll
                for (int nt = 0; nt < 2; nt++)
#pragma unroll
                    for (int o = 0; o < 2; o++)
                        mma_bf16(c[mt][nt * 2 + o], AhF[mt], BlF[nt][o], BlF[nt][o + 2]);
#pragma unroll
            for (int mt = 0; mt < 2; mt++)
#pragma unroll
                for (int nt = 0; nt < 2; nt++)
#pragma unroll
                    for (int o = 0; o < 2; o++)
                        mma_bf16(c[mt][nt * 2 + o], AlF[mt], BhF[nt][o], BhF[nt][o + 2]);

            if (ks == 0 && ck + 1 < 16) {
                uint32_t st = sb + (uint32_t)((ck + 1) & 1) * GS_STAGE;
                const int k0 = (ck + 1) * 64;
                at_load128(st + GS_AHI, Ah + k0, tid);
                at_load128(st + GS_ALO, Al + k0, tid);
                at_load64(st + GS_BHI, Bh + k0, tid);
                at_load64(st + GS_BLO, Bl + k0, tid);
                asm volatile("cp.async.commit_group;");
            }
        }
    }

    const int cl = 2 * (lane & 3);
    if (mode == 0) {
        const float scale = (z == 0) ? 0.125f * 1.4426950408889634f : 1.0f;
        __nv_bfloat16* Hi = g_QKVhi + (size_t)z * MROWS * DMODEL;
        __nv_bfloat16* Lo = g_QKVlo + (size_t)z * MROWS * DMODEL;
#pragma unroll
        for (int mt = 0; mt < 2; mt++) {
            const int r0 = rowBase + wm + mt * 16 + (lane >> 2);
#pragma unroll
            for (int nf = 0; nf < 4; nf++) {
                const int col = colBase + wn + nf * 8 + cl;
                uint32_t h0, l0, h1, l1;
                split_pack(c[mt][nf][0] * scale, c[mt][nf][1] * scale, h0, l0);
                split_pack(c[mt][nf][2] * scale, c[mt][nf][3] * scale, h1, l1);
                *(uint32_t*)&Hi[(size_t)r0 * DMODEL + col] = h0;
                *(uint32_t*)&Lo[(size_t)r0 * DMODEL + col] = l0;
                *(uint32_t*)&Hi[(size_t)(r0 + 8) * DMODEL + col] = h1;
                *(uint32_t*)&Lo[(size_t)(r0 + 8) * DMODEL + col] = l1;
            }
        }
    } else {
#pragma unroll
        for (int mt = 0; mt < 2; mt++) {
            const int r0 = rowBase + wm + mt * 16 + (lane >> 2);
#pragma unroll
            for (int nf = 0; nf < 4; nf++) {
                const int col = colBase + wn + nf * 8 + cl;
                const float b0 = biasp[col], b1 = biasp[col + 1];
                float2 v0 = make_float2(c[mt][nf][0] + b0, c[mt][nf][1] + b1);
                float2 v1 = make_float2(c[mt][nf][2] + b0, c[mt][nf][3] + b1);
                *(float2*)&outp[(size_t)r0 * DMODEL + col] = v0;
                *(float2*)&outp[(size_t)(r0 + 8) * DMODEL + col] = v1;
            }
        }
    }
}

// ---------------------------------------------------------------------------
// Tensor-core causal flash attention (exact R11 form — best known).
// ---------------------------------------------------------------------------
#define AT_STAGE 32768
#define AT_KHI   0
#define AT_KLO   8192
#define AT_VHI   16384
#define AT_VLO   24576
#define AT_QHI   65536
#define AT_QLO   81920
#define AT_TOTAL 98304

__global__ __launch_bounds__(256) void attn_kernel() {
    uint32_t sb = smem_u32(dyn_smem);
    const int tid = threadIdx.x, lane = tid & 31, wid = tid >> 5;
    const int qt = blockIdx.x, bh = blockIdx.y;
    const int b = bh >> 4, h = bh & 15;
    const int wm = wid * 16;
    const int rA = lane & 15, cb16 = (lane >> 4) << 4;
    const int jmax = 2 * qt + 1;

    const size_t qoff = ((size_t)b * S_LEN + qt * 128) * DMODEL + h * HDIM;
    const __nv_bfloat16* Qh_g = g_QKVhi + qoff;
    const __nv_bfloat16* Ql_g = g_QKVlo + qoff;
    const size_t kvbase = (size_t)b * S_LEN * DMODEL + h * HDIM;
    const __nv_bfloat16* Kh_g = g_QKVhi + (size_t)MROWS * DMODEL + kvbase;
    const __nv_bfloat16* Kl_g = g_QKVlo + (size_t)MROWS * DMODEL + kvbase;
    const __nv_bfloat16* Vh_g = g_QKVhi + (size_t)2 * MROWS * DMODEL + kvbase;
    const __nv_bfloat16* Vl_g = g_QKVlo + (size_t)2 * MROWS * DMODEL + kvbase;

    at_load128(sb + AT_QHI, Qh_g, tid);
    at_load128(sb + AT_QLO, Ql_g, tid);
    at_load64(sb + AT_KHI, Kh_g, tid);
    at_load64(sb + AT_KLO, Kl_g, tid);
    at_load64(sb + AT_VHI, Vh_g, tid);
    at_load64(sb + AT_VLO, Vl_g, tid);
    asm volatile("cp.async.commit_group;");

    float co[8][4];
#pragma unroll
    for (int i = 0; i < 8; i++)
#pragma unroll
        for (int j = 0; j < 4; j++) co[i][j] = 0.f;
    float m_i[2] = {-INFINITY, -INFINITY};
    float l_i[2] = {0.f, 0.f};
    uint32_t QhF[4][4], QlF[4][4];

    for (int j = 0; j <= jmax; j++) {
        asm volatile("cp.async.wait_group 0;");
        __syncthreads();

        if (j + 1 <= jmax) {
            uint32_t stn = sb + (uint32_t)((j + 1) & 1) * AT_STAGE;
            const size_t ro = (size_t)(j + 1) * 64 * DMODEL;
            at_load64(stn + AT_KHI, Kh_g + ro, tid);
            at_load64(stn + AT_KLO, Kl_g + ro, tid);
            at_load64(stn + AT_VHI, Vh_g + ro, tid);
            at_load64(stn + AT_VLO, Vl_g + ro, tid);
            asm volatile("cp.async.commit_group;");
        }

        if (j == 0) {
#pragma unroll
            for (int ks = 0; ks < 4; ks++) {
                uint32_t off = sw128((uint32_t)((wm + rA) * 128 + ks * 32 + cb16));
                ldsm_x4(QhF[ks], sb + AT_QHI + off);
                ldsm_x4(QlF[ks], sb + AT_QLO + off);
            }
        }

        const int qmin = qt * 128 + wm;
        if (j * 64 > qmin + 15) continue;

        const uint32_t st = sb + (uint32_t)(j & 1) * AT_STAGE;

        float cs[8][4];
#pragma unroll
        for (int i = 0; i < 8; i++)
#pragma unroll
            for (int e = 0; e < 4; e++) cs[i][e] = 0.f;
#pragma unroll
        for (int ks = 0; ks < 4; ks++) {
#pragma unroll
            for (int nt = 0; nt < 4; nt++) {
                uint32_t kh[4], kl[4];
                uint32_t off = sw128((uint32_t)((nt * 16 + rA) * 128 + ks * 32 + cb16));
                ldsm_x4(kh, st + AT_KHI + off);
                ldsm_x4(kl, st + AT_KLO + off);
#pragma unroll
                for (int o = 0; o < 2; o++) {
                    mma_bf16(cs[nt * 2 + o], QhF[ks], kh[o], kh[o + 2]);
                    mma_bf16(cs[nt * 2 + o], QhF[ks], kl[o], kl[o + 2]);
                    mma_bf16(cs[nt * 2 + o], QlF[ks], kh[o], kh[o + 2]);
                }
            }
        }

        if (j * 64 + 63 > qmin) {
            const int r0 = lane >> 2, c0 = 2 * (lane & 3);
#pragma unroll
            for (int nf = 0; nf < 8; nf++) {
#pragma unroll
                for (int e = 0; e < 4; e++) {
                    const int col = nf * 8 + c0 + (e & 1);
                    const int row = r0 + ((e >> 1) * 8);
                    if (j * 64 + col > qmin + row) cs[nf][e] = -1e30f;
                }
            }
        }

        float mx0 = -INFINITY, mx1 = -INFINITY;
#pragma unroll
        for (int nf = 0; nf < 8; nf++) {
            mx0 = fmaxf(mx0, fmaxf(cs[nf][0], cs[nf][1]));
            mx1 = fmaxf(mx1, fmaxf(cs[nf][2], cs[nf][3]));
        }
        mx0 = fmaxf(mx0, __shfl_xor_sync(0xffffffffu, mx0, 1));
        mx0 = fmaxf(mx0, __shfl_xor_sync(0xffffffffu, mx0, 2));
        mx1 = fmaxf(mx1, __shfl_xor_sync(0xffffffffu, mx1, 1));
        mx1 = fmaxf(mx1, __shfl_xor_sync(0xffffffffu, mx1, 2));
        const float mn0 = fmaxf(m_i[0], mx0), mn1 = fmaxf(m_i[1], mx1);
        const float corr0 = ex2f(m_i[0] - mn0), corr1 = ex2f(m_i[1] - mn1);
        float rs0 = 0.f, rs1 = 0.f;
#pragma unroll
        for (int nf = 0; nf < 8; nf++) {
            cs[nf][0] = ex2f(cs[nf][0] - mn0); rs0 += cs[nf][0];
            cs[nf][1] = ex2f(cs[nf][1] - mn0); rs0 += cs[nf][1];
            cs[nf][2] = ex2f(cs[nf][2] - mn1); rs1 += cs[nf][2];
            cs[nf][3] = ex2f(cs[nf][3] - mn1); rs1 += cs[nf][3];
        }
        rs0 += __shfl_xor_sync(0xffffffffu, rs0, 1);
        rs0 += __shfl_xor_sync(0xffffffffu, rs0, 2);
        rs1 += __shfl_xor_sync(0xffffffffu, rs1, 1);
        rs1 += __shfl_xor_sync(0xffffffffu, rs1, 2);
        l_i[0] = l_i[0] * corr0 + rs0; m_i[0] = mn0;
        l_i[1] = l_i[1] * corr1 + rs1; m_i[1] = mn1;
#pragma unroll
        for (int nf = 0; nf < 8; nf++) {
            co[nf][0] *= corr0; co[nf][1] *= corr0;
            co[nf][2] *= corr1; co[nf][3] *= corr1;
        }

#pragma unroll
        for (int kt = 0; kt < 4; kt++) {
            uint32_t pah[4], pal[4];
            split_pack(cs[2 * kt][0],     cs[2 * kt][1],     pah[0], pal[0]);
            split_pack(cs[2 * kt][2],     cs[2 * kt][3],     pah[1], pal[1]);
            split_pack(cs[2 * kt + 1][0], cs[2 * kt + 1][1], pah[2], pal[2]);
            split_pack(cs[2 * kt + 1][2], cs[2 * kt + 1][3], pah[3], pal[3]);
#pragma unroll
            for (int nt = 0; nt < 4; nt++) {
                uint32_t vh[4], vl[4];
                uint32_t off = sw128((uint32_t)((kt * 16 + rA) * 128 + nt * 32 + cb16));
                ldsm_x4_t(vh, st + AT_VHI + off);
                ldsm_x4_t(vl, st + AT_VLO + off);
                mma_bf16(co[nt * 2 + 0], pah, vh[0], vh[1]);
                mma_bf16(co[nt * 2 + 0], pah, vl[0], vl[1]);
                mma_bf16(co[nt * 2 + 0], pal, vh[0], vh[1]);
                mma_bf16(co[nt * 2 + 1], pah, vh[2], vh[3]);
                mma_bf16(co[nt * 2 + 1], pah, vl[2], vl[3]);
                mma_bf16(co[nt * 2 + 1], pal, vh[2], vh[3]);
            }
        }
    }

    const float inv0 = 1.f / l_i[0], inv1 = 1.f / l_i[1];
    const int row0 = b * S_LEN + qt * 128 + wm + (lane >> 2);
    const int colb = h * HDIM + 2 * (lane & 3);
#pragma unroll
    for (int nf = 0; nf < 8; nf++) {
        const int col = colb + nf * 8;
        uint32_t h0, l0, h1, l1;
        split_pack(co[nf][0] * inv0, co[nf][1] * inv0, h0, l0);
        split_pack(co[nf][2] * inv1, co[nf][3] * inv1, h1, l1);
        *(uint32_t*)&g_Chi[(size_t)row0 * DMODEL + col] = h0;
        *(uint32_t*)&g_Clo[(size_t)row0 * DMODEL + col] = l0;
        *(uint32_t*)&g_Chi[(size_t)(row0 + 8) * DMODEL + col] = h1;
        *(uint32_t*)&g_Clo[(size_t)(row0 + 8) * DMODEL + col] = l1;
    }
}

// ---------------------------------------------------------------------------
extern "C" void kernel_launch(void* const* d_in, const int* in_sizes, int n_in,
                              void* d_out, int out_size)
{
    const float* x  = (const float*)d_in[0];
    const float* Wq = (const float*)d_in[1];
    const float* Wk = (const float*)d_in[2];
    const float* Wv = (const float*)d_in[3];
    const float* Wo = (const float*)d_in[4];
    const float* bo = (const float*)d_in[5];
    float* out = (float*)d_out;

    cudaFuncSetAttribute(gemm_kernel, cudaFuncAttributeMaxDynamicSharedMemorySize, GS_TOTAL);
    cudaFuncSetAttribute(attn_kernel, cudaFuncAttributeMaxDynamicSharedMemorySize, AT_TOTAL);

    split_kernel<<<(MROWS * DMODEL + 255) / 256, 256>>>(x, MROWS * DMODEL, 0);
    split_kernel<<<(DMODEL * DMODEL + 255) / 256, 256>>>(Wo, DMODEL * DMODEL, 1);
    tsplit_kernel<<<dim3(32, 32, 3), dim3(32, 8)>>>(Wq, Wk, Wv);

    gemm_kernel<<<dim3(DMODEL / 64, MROWS / 128, 3), 256, GS_TOTAL>>>(0, nullptr, nullptr);

    attn_kernel<<<dim3(S_LEN / 128, BATCH * NHEADS), 256, AT_TOTAL>>>();

    gemm_kernel<<<dim3(DMODEL / 64, MROWS / 128, 1), 256, GS_TOTAL>>>(1, out, bo);
}

// round 14
// speedup vs baseline: 1.3979x; 1.3668x over previous
#include <cuda_runtime.h>
#include <cuda_fp16.h>
#include <math.h>
#include <stdint.h>

#define S_LEN   2048
#define DMODEL  1024
#define NHEADS  16
#define HDIM    64
#define BATCH   2
#define MROWS   (BATCH * S_LEN)   // 4096

extern __shared__ __align__(128) float dyn_smem[];

// ---------------------------------------------------------------------------
// Global scratch (fp16). A-side operands: hi only. B-side: hi+lo.
// ---------------------------------------------------------------------------
__device__ __align__(128) __half g_Xhi[MROWS * DMODEL];
__device__ __align__(128) __half g_Wthi[3 * DMODEL * DMODEL];
__device__ __align__(128) __half g_Wtlo[3 * DMODEL * DMODEL];
__device__ __align__(128) __half g_Wohi[DMODEL * DMODEL];
__device__ __align__(128) __half g_Wolo[DMODEL * DMODEL];
__device__ __align__(128) __half g_Chi[MROWS * DMODEL];
__device__ __align__(128) __half g_QKVhi[3 * MROWS * DMODEL];  // Q scaled by 0.125*log2e
__device__ __align__(128) __half g_QKVlo[3 * MROWS * DMODEL];  // lo used for K,V only

// ---------------------------------------------------------------------------
// Helpers
// ---------------------------------------------------------------------------
__device__ __forceinline__ uint32_t smem_u32(const void* p) {
    uint32_t a;
    asm("{ .reg .u64 t; cvta.to.shared.u64 t, %1; cvt.u32.u64 %0, t; }" : "=r"(a) : "l"(p));
    return a;
}
__device__ __forceinline__ void ldsm_x4(uint32_t* r, uint32_t addr) {
    asm volatile("ldmatrix.sync.aligned.m8n8.x4.shared.b16 {%0,%1,%2,%3}, [%4];"
                 : "=r"(r[0]), "=r"(r[1]), "=r"(r[2]), "=r"(r[3]) : "r"(addr));
}
__device__ __forceinline__ void ldsm_x4_t(uint32_t* r, uint32_t addr) {
    asm volatile("ldmatrix.sync.aligned.m8n8.x4.trans.shared.b16 {%0,%1,%2,%3}, [%4];"
                 : "=r"(r[0]), "=r"(r[1]), "=r"(r[2]), "=r"(r[3]) : "r"(addr));
}
__device__ __forceinline__ void mma_f16(float* c, const uint32_t* a, uint32_t b0, uint32_t b1) {
    asm volatile(
        "mma.sync.aligned.m16n8k16.row.col.f32.f16.f16.f32 "
        "{%0,%1,%2,%3},{%4,%5,%6,%7},{%8,%9},{%0,%1,%2,%3};"
        : "+f"(c[0]), "+f"(c[1]), "+f"(c[2]), "+f"(c[3])
        : "r"(a[0]), "r"(a[1]), "r"(a[2]), "r"(a[3]), "r"(b0), "r"(b1));
}
__device__ __forceinline__ float ex2f(float x) {
    float r;
    asm("ex2.approx.f32 %0, %1;" : "=f"(r) : "f"(x));
    return r;
}
__device__ __forceinline__ uint32_t pack_h2(float a, float b) {
    __half2 t = __floats2half2_rn(a, b);   // a -> low half
    return *(uint32_t*)&t;
}
// fp16 hi/lo split-pack
__device__ __forceinline__ void split_pack_h(float a, float b, uint32_t& oh, uint32_t& ol) {
    __half ha = __float2half(a), hb = __float2half(b);
    float la = a - __half2float(ha), lb = b - __half2float(hb);
    __half2 th = __halves2half2(ha, hb);
    __half2 tl = __halves2half2(__float2half(la), __float2half(lb));
    oh = *(uint32_t*)&th; ol = *(uint32_t*)&tl;
}
__device__ __forceinline__ uint32_t sw128(uint32_t off) {
    return off ^ ((off >> 3) & 0x70);
}

// ---------------------------------------------------------------------------
// Pre-pass splits
// ---------------------------------------------------------------------------
__global__ void splitx_kernel(const float* __restrict__ src, int n) {
    int i = blockIdx.x * 256 + threadIdx.x;
    if (i < n) g_Xhi[i] = __float2half(src[i]);
}
__global__ void splitwo_kernel(const float* __restrict__ src, int n) {
    int i = blockIdx.x * 256 + threadIdx.x;
    if (i < n) {
        float a = src[i];
        __half h = __float2half(a);
        g_Wohi[i] = h;
        g_Wolo[i] = __float2half(a - __half2float(h));
    }
}
__global__ void tsplit_kernel(const float* __restrict__ Wq,
                              const float* __restrict__ Wk,
                              const float* __restrict__ Wv) {
    const float* W = (blockIdx.z == 0) ? Wq : (blockIdx.z == 1) ? Wk : Wv;
    __half* Hi = g_Wthi + (size_t)blockIdx.z * DMODEL * DMODEL;
    __half* Lo = g_Wtlo + (size_t)blockIdx.z * DMODEL * DMODEL;
    __shared__ float t[32][33];
    const int k0 = blockIdx.y * 32, n0 = blockIdx.x * 32;
    const int tx = threadIdx.x, ty = threadIdx.y;
#pragma unroll
    for (int r = 0; r < 4; r++)
        t[ty + 8 * r][tx] = W[(size_t)(k0 + ty + 8 * r) * DMODEL + n0 + tx];
    __syncthreads();
#pragma unroll
    for (int r = 0; r < 4; r++) {
        float a = t[tx][ty + 8 * r];
        size_t idx = (size_t)(n0 + ty + 8 * r) * DMODEL + k0 + tx;
        __half h = __float2half(a);
        Hi[idx] = h;
        Lo[idx] = __float2half(a - __half2float(h));
    }
}

// ---------------------------------------------------------------------------
// Tile loaders
// ---------------------------------------------------------------------------
__device__ __forceinline__ void at_load64(uint32_t sdst, const __half* g, int tid) {
#pragma unroll
    for (int t = 0; t < 2; t++) {
        int cid = t * 256 + tid;
        int r = cid >> 3, ch = cid & 7;
        uint32_t off = sw128((uint32_t)(r * 128 + ch * 16));
        const char* src = (const char*)(g + (size_t)r * DMODEL) + ch * 16;
        asm volatile("cp.async.cg.shared.global [%0], [%1], 16;" :: "r"(sdst + off), "l"(src));
    }
}
__device__ __forceinline__ void at_load128(uint32_t sdst, const __half* g, int tid) {
#pragma unroll
    for (int t = 0; t < 4; t++) {
        int cid = t * 256 + tid;
        int r = cid >> 3, ch = cid & 7;
        uint32_t off = sw128((uint32_t)(r * 128 + ch * 16));
        const char* src = (const char*)(g + (size_t)r * DMODEL) + ch * 16;
        asm volatile("cp.async.cg.shared.global [%0], [%1], 16;" :: "r"(sdst + off), "l"(src));
    }
}

// ---------------------------------------------------------------------------
// fp16 2-term mma GEMM: C = A_hi * (B_hi + B_lo)^T. 128x64 tile, 2 CTAs/SM.
// stage: Ahi 16K | Bhi 8K | Blo 8K = 32K; 2 stages = 64K
// ---------------------------------------------------------------------------
#define GS_STAGE 32768
#define GS_AHI   0
#define GS_BHI   16384
#define GS_BLO   24576
#define GS_TOTAL (2 * GS_STAGE)   // 65536

__global__ __launch_bounds__(256, 2) void gemm_kernel(int mode, float* __restrict__ outp,
                                                      const float* __restrict__ biasp) {
    uint32_t sb = smem_u32(dyn_smem);
    const int tid = threadIdx.x, lane = tid & 31, wid = tid >> 5;
    const int wm = (wid >> 1) * 32;
    const int wn = (wid & 1) * 32;
    const int rowBase = blockIdx.y * 128;
    const int colBase = blockIdx.x * 64;
    const int z = blockIdx.z;
    const int rA = lane & 15, cb16 = (lane >> 4) << 4;

    const __half *Ah, *Bh, *Bl;
    if (mode == 0) {
        Ah = g_Xhi;
        Bh = g_Wthi + (size_t)z * DMODEL * DMODEL;
        Bl = g_Wtlo + (size_t)z * DMODEL * DMODEL;
    } else {
        Ah = g_Chi;
        Bh = g_Wohi; Bl = g_Wolo;
    }
    Ah += (size_t)rowBase * DMODEL;
    Bh += (size_t)colBase * DMODEL;
    Bl += (size_t)colBase * DMODEL;

    uint32_t aOff[2][4], bOff[2][4];
#pragma unroll
    for (int mt = 0; mt < 2; mt++)
#pragma unroll
        for (int ks = 0; ks < 4; ks++)
            aOff[mt][ks] = sw128((uint32_t)((wm + mt * 16 + rA) * 128 + ks * 32 + cb16));
#pragma unroll
    for (int nt = 0; nt < 2; nt++)
#pragma unroll
        for (int ks = 0; ks < 4; ks++)
            bOff[nt][ks] = sw128((uint32_t)((wn + nt * 16 + rA) * 128 + ks * 32 + cb16));

    float c[2][4][4];
#pragma unroll
    for (int i = 0; i < 2; i++)
#pragma unroll
        for (int j = 0; j < 4; j++)
#pragma unroll
            for (int k = 0; k < 4; k++) c[i][j][k] = 0.f;

    at_load128(sb + GS_AHI, Ah, tid);
    at_load64(sb + GS_BHI, Bh, tid);
    at_load64(sb + GS_BLO, Bl, tid);
    asm volatile("cp.async.commit_group;");

    for (int ck = 0; ck < 16; ck++) {
        const int s = ck & 1;
        asm volatile("cp.async.wait_group 0;");
        __syncthreads();

        const uint32_t aHi = sb + (uint32_t)s * GS_STAGE + GS_AHI;
        const uint32_t bHi = sb + (uint32_t)s * GS_STAGE + GS_BHI;
        const uint32_t bLo = sb + (uint32_t)s * GS_STAGE + GS_BLO;

#pragma unroll
        for (int ks = 0; ks < 4; ks++) {
            uint32_t AhF[2][4], BhF[2][4], BlF[2][4];
#pragma unroll
            for (int mt = 0; mt < 2; mt++)
                ldsm_x4(AhF[mt], aHi + aOff[mt][ks]);
#pragma unroll
            for (int nt = 0; nt < 2; nt++) {
                ldsm_x4(BhF[nt], bHi + bOff[nt][ks]);
                ldsm_x4(BlF[nt], bLo + bOff[nt][ks]);
            }
#pragma unroll
            for (int mt = 0; mt < 2; mt++)
#pragma unroll
                for (int nt = 0; nt < 2; nt++)
#pragma unroll
                    for (int o = 0; o < 2; o++) {
                        mma_f16(c[mt][nt * 2 + o], AhF[mt], BhF[nt][o], BhF[nt][o + 2]);
                        mma_f16(c[mt][nt * 2 + o], AhF[mt], BlF[nt][o], BlF[nt][o + 2]);
                    }

            if (ks == 0 && ck + 1 < 16) {
                uint32_t st = sb + (uint32_t)((ck + 1) & 1) * GS_STAGE;
                const int k0 = (ck + 1) * 64;
                at_load128(st + GS_AHI, Ah + k0, tid);
                at_load64(st + GS_BHI, Bh + k0, tid);
                at_load64(st + GS_BLO, Bl + k0, tid);
                asm volatile("cp.async.commit_group;");
            }
        }
    }

    const int cl = 2 * (lane & 3);
    if (mode == 0) {
        const float scale = (z == 0) ? 0.125f * 1.4426950408889634f : 1.0f;
        __half* Hi = g_QKVhi + (size_t)z * MROWS * DMODEL;
        __half* Lo = g_QKVlo + (size_t)z * MROWS * DMODEL;
        const bool needLo = (z != 0);   // lo used only for K and V
#pragma unroll
        for (int mt = 0; mt < 2; mt++) {
            const int r0 = rowBase + wm + mt * 16 + (lane >> 2);
#pragma unroll
            for (int nf = 0; nf < 4; nf++) {
                const int col = colBase + wn + nf * 8 + cl;
                uint32_t h0, l0, h1, l1;
                split_pack_h(c[mt][nf][0] * scale, c[mt][nf][1] * scale, h0, l0);
                split_pack_h(c[mt][nf][2] * scale, c[mt][nf][3] * scale, h1, l1);
                *(uint32_t*)&Hi[(size_t)r0 * DMODEL + col] = h0;
                *(uint32_t*)&Hi[(size_t)(r0 + 8) * DMODEL + col] = h1;
                if (needLo) {
                    *(uint32_t*)&Lo[(size_t)r0 * DMODEL + col] = l0;
                    *(uint32_t*)&Lo[(size_t)(r0 + 8) * DMODEL + col] = l1;
                }
            }
        }
    } else {
#pragma unroll
        for (int mt = 0; mt < 2; mt++) {
            const int r0 = rowBase + wm + mt * 16 + (lane >> 2);
#pragma unroll
            for (int nf = 0; nf < 4; nf++) {
                const int col = colBase + wn + nf * 8 + cl;
                const float b0 = biasp[col], b1 = biasp[col + 1];
                float2 v0 = make_float2(c[mt][nf][0] + b0, c[mt][nf][1] + b1);
                float2 v1 = make_float2(c[mt][nf][2] + b0, c[mt][nf][3] + b1);
                *(float2*)&outp[(size_t)r0 * DMODEL + col] = v0;
                *(float2*)&outp[(size_t)(r0 + 8) * DMODEL + col] = v1;
            }
        }
    }
}

// ---------------------------------------------------------------------------
// fp16 flash attention: S = Qh*(Kh+Kl), O += Ph*(Vh+Vl). exp2 softmax.
// smem: 2 x KV stage 32K | Qhi 16K = 80K -> 2 CTAs/SM.
// ---------------------------------------------------------------------------
#define AT_STAGE 32768
#define AT_KHI   0
#define AT_KLO   8192
#define AT_VHI   16384
#define AT_VLO   24576
#define AT_QHI   65536
#define AT_TOTAL 81920

__global__ __launch_bounds__(256, 2) void attn_kernel() {
    uint32_t sb = smem_u32(dyn_smem);
    const int tid = threadIdx.x, lane = tid & 31, wid = tid >> 5;
    const int qt = blockIdx.x, bh = blockIdx.y;
    const int b = bh >> 4, h = bh & 15;
    const int wm = wid * 16;
    const int rA = lane & 15, cb16 = (lane >> 4) << 4;
    const int jmax = 2 * qt + 1;

    const size_t qoff = ((size_t)b * S_LEN + qt * 128) * DMODEL + h * HDIM;
    const __half* Qh_g = g_QKVhi + qoff;
    const size_t kvbase = (size_t)b * S_LEN * DMODEL + h * HDIM;
    const __half* Kh_g = g_QKVhi + (size_t)MROWS * DMODEL + kvbase;
    const __half* Kl_g = g_QKVlo + (size_t)MROWS * DMODEL + kvbase;
    const __half* Vh_g = g_QKVhi + (size_t)2 * MROWS * DMODEL + kvbase;
    const __half* Vl_g = g_QKVlo + (size_t)2 * MROWS * DMODEL + kvbase;

    at_load128(sb + AT_QHI, Qh_g, tid);
    at_load64(sb + AT_KHI, Kh_g, tid);
    at_load64(sb + AT_KLO, Kl_g, tid);
    at_load64(sb + AT_VHI, Vh_g, tid);
    at_load64(sb + AT_VLO, Vl_g, tid);
    asm volatile("cp.async.commit_group;");

    float co[8][4];
#pragma unroll
    for (int i = 0; i < 8; i++)
#pragma unroll
        for (int j = 0; j < 4; j++) co[i][j] = 0.f;
    float m_i[2] = {-INFINITY, -INFINITY};
    float l_i[2] = {0.f, 0.f};
    uint32_t QhF[4][4];

    for (int j = 0; j <= jmax; j++) {
        asm volatile("cp.async.wait_group 0;");
        __syncthreads();

        if (j + 1 <= jmax) {
            uint32_t stn = sb + (uint32_t)((j + 1) & 1) * AT_STAGE;
            const size_t ro = (size_t)(j + 1) * 64 * DMODEL;
            at_load64(stn + AT_KHI, Kh_g + ro, tid);
            at_load64(stn + AT_KLO, Kl_g + ro, tid);
            at_load64(stn + AT_VHI, Vh_g + ro, tid);
            at_load64(stn + AT_VLO, Vl_g + ro, tid);
            asm volatile("cp.async.commit_group;");
        }

        if (j == 0) {
#pragma unroll
            for (int ks = 0; ks < 4; ks++) {
                uint32_t off = sw128((uint32_t)((wm + rA) * 128 + ks * 32 + cb16));
                ldsm_x4(QhF[ks], sb + AT_QHI + off);
            }
        }

        const int qmin = qt * 128 + wm;
        if (j * 64 > qmin + 15) continue;

        const uint32_t st = sb + (uint32_t)(j & 1) * AT_STAGE;

        // ---- S = Qh (Kh + Kl)^T ----
        float cs[8][4];
#pragma unroll
        for (int i = 0; i < 8; i++)
#pragma unroll
            for (int e = 0; e < 4; e++) cs[i][e] = 0.f;
#pragma unroll
        for (int ks = 0; ks < 4; ks++) {
#pragma unroll
            for (int nt = 0; nt < 4; nt++) {
                uint32_t kh[4], kl[4];
                uint32_t off = sw128((uint32_t)((nt * 16 + rA) * 128 + ks * 32 + cb16));
                ldsm_x4(kh, st + AT_KHI + off);
                ldsm_x4(kl, st + AT_KLO + off);
#pragma unroll
                for (int o = 0; o < 2; o++) {
                    mma_f16(cs[nt * 2 + o], QhF[ks], kh[o], kh[o + 2]);
                    mma_f16(cs[nt * 2 + o], QhF[ks], kl[o], kl[o + 2]);
                }
            }
        }

        if (j * 64 + 63 > qmin) {
            const int r0 = lane >> 2, c0 = 2 * (lane & 3);
#pragma unroll
            for (int nf = 0; nf < 8; nf++) {
#pragma unroll
                for (int e = 0; e < 4; e++) {
                    const int col = nf * 8 + c0 + (e & 1);
                    const int row = r0 + ((e >> 1) * 8);
                    if (j * 64 + col > qmin + row) cs[nf][e] = -1e30f;
                }
            }
        }

        // ---- online softmax (exp2 domain) ----
        float mx0 = -INFINITY, mx1 = -INFINITY;
#pragma unroll
        for (int nf = 0; nf < 8; nf++) {
            mx0 = fmaxf(mx0, fmaxf(cs[nf][0], cs[nf][1]));
            mx1 = fmaxf(mx1, fmaxf(cs[nf][2], cs[nf][3]));
        }
        mx0 = fmaxf(mx0, __shfl_xor_sync(0xffffffffu, mx0, 1));
        mx0 = fmaxf(mx0, __shfl_xor_sync(0xffffffffu, mx0, 2));
        mx1 = fmaxf(mx1, __shfl_xor_sync(0xffffffffu, mx1, 1));
        mx1 = fmaxf(mx1, __shfl_xor_sync(0xffffffffu, mx1, 2));
        const float mn0 = fmaxf(m_i[0], mx0), mn1 = fmaxf(m_i[1], mx1);
        const float corr0 = ex2f(m_i[0] - mn0), corr1 = ex2f(m_i[1] - mn1);
        float rs0 = 0.f, rs1 = 0.f;
#pragma unroll
        for (int nf = 0; nf < 8; nf++) {
            cs[nf][0] = ex2f(cs[nf][0] - mn0); rs0 += cs[nf][0];
            cs[nf][1] = ex2f(cs[nf][1] - mn0); rs0 += cs[nf][1];
            cs[nf][2] = ex2f(cs[nf][2] - mn1); rs1 += cs[nf][2];
            cs[nf][3] = ex2f(cs[nf][3] - mn1); rs1 += cs[nf][3];
        }
        rs0 += __shfl_xor_sync(0xffffffffu, rs0, 1);
        rs0 += __shfl_xor_sync(0xffffffffu, rs0, 2);
        rs1 += __shfl_xor_sync(0xffffffffu, rs1, 1);
        rs1 += __shfl_xor_sync(0xffffffffu, rs1, 2);
        l_i[0] = l_i[0] * corr0 + rs0; m_i[0] = mn0;
        l_i[1] = l_i[1] * corr1 + rs1; m_i[1] = mn1;
#pragma unroll
        for (int nf = 0; nf < 8; nf++) {
            co[nf][0] *= corr0; co[nf][1] *= corr0;
            co[nf][2] *= corr1; co[nf][3] *= corr1;
        }

        // ---- O += Ph (Vh + Vl) ----
#pragma unroll
        for (int kt = 0; kt < 4; kt++) {
            uint32_t pah[4];
            pah[0] = pack_h2(cs[2 * kt][0],     cs[2 * kt][1]);
            pah[1] = pack_h2(cs[2 * kt][2],     cs[2 * kt][3]);
            pah[2] = pack_h2(cs[2 * kt + 1][0], cs[2 * kt + 1][1]);
            pah[3] = pack_h2(cs[2 * kt + 1][2], cs[2 * kt + 1][3]);
#pragma unroll
            for (int nt = 0; nt < 4; nt++) {
                uint32_t vh[4], vl[4];
                uint32_t off = sw128((uint32_t)((kt * 16 + rA) * 128 + nt * 32 + cb16));
                ldsm_x4_t(vh, st + AT_VHI + off);
                ldsm_x4_t(vl, st + AT_VLO + off);
                mma_f16(co[nt * 2 + 0], pah, vh[0], vh[1]);
                mma_f16(co[nt * 2 + 0], pah, vl[0], vl[1]);
                mma_f16(co[nt * 2 + 1], pah, vh[2], vh[3]);
                mma_f16(co[nt * 2 + 1], pah, vl[2], vl[3]);
            }
        }
    }

    // ---- epilogue: ctx -> fp16 hi (only) ----
    const float inv0 = 1.f / l_i[0], inv1 = 1.f / l_i[1];
    const int row0 = b * S_LEN + qt * 128 + wm + (lane >> 2);
    const int colb = h * HDIM + 2 * (lane & 3);
#pragma unroll
    for (int nf = 0; nf < 8; nf++) {
        const int col = colb + nf * 8;
        *(uint32_t*)&g_Chi[(size_t)row0 * DMODEL + col] =
            pack_h2(co[nf][0] * inv0, co[nf][1] * inv0);
        *(uint32_t*)&g_Chi[(size_t)(row0 + 8) * DMODEL + col] =
            pack_h2(co[nf][2] * inv1, co[nf][3] * inv1);
    }
}

// ---------------------------------------------------------------------------
extern "C" void kernel_launch(void* const* d_in, const int* in_sizes, int n_in,
                              void* d_out, int out_size)
{
    const float* x  = (const float*)d_in[0];
    const float* Wq = (const float*)d_in[1];
    const float* Wk = (const float*)d_in[2];
    const float* Wv = (const float*)d_in[3];
    const float* Wo = (const float*)d_in[4];
    const float* bo = (const float*)d_in[5];
    float* out = (float*)d_out;

    cudaFuncSetAttribute(gemm_kernel, cudaFuncAttributeMaxDynamicSharedMemorySize, GS_TOTAL);
    cudaFuncSetAttribute(attn_kernel, cudaFuncAttributeMaxDynamicSharedMemorySize, AT_TOTAL);

    splitx_kernel<<<(MROWS * DMODEL + 255) / 256, 256>>>(x, MROWS * DMODEL);
    splitwo_kernel<<<(DMODEL * DMODEL + 255) / 256, 256>>>(Wo, DMODEL * DMODEL);
    tsplit_kernel<<<dim3(32, 32, 3), dim3(32, 8)>>>(Wq, Wk, Wv);

    gemm_kernel<<<dim3(DMODEL / 64, MROWS / 128, 3), 256, GS_TOTAL>>>(0, nullptr, nullptr);

    attn_kernel<<<dim3(S_LEN / 128, BATCH * NHEADS), 256, AT_TOTAL>>>();

    gemm_kernel<<<dim3(DMODEL / 64, MROWS / 128, 1), 256, GS_TOTAL>>>(1, out, bo);
}

// round 16
// speedup vs baseline: 1.4274x; 1.0211x over previous
#include <cuda_runtime.h>
#include <cuda_fp16.h>
#include <math.h>
#include <stdint.h>

#define S_LEN   2048
#define DMODEL  1024
#define NHEADS  16
#define HDIM    64
#define BATCH   2
#define MROWS   (BATCH * S_LEN)   // 4096

extern __shared__ __align__(128) float dyn_smem[];

// ---------------------------------------------------------------------------
// Global scratch (fp16). A-side operands: hi only. B-side: hi+lo.
// ---------------------------------------------------------------------------
__device__ __align__(128) __half g_Xhi[MROWS * DMODEL];
__device__ __align__(128) __half g_Wthi[3 * DMODEL * DMODEL];
__device__ __align__(128) __half g_Wtlo[3 * DMODEL * DMODEL];
__device__ __align__(128) __half g_Wohi[DMODEL * DMODEL];
__device__ __align__(128) __half g_Wolo[DMODEL * DMODEL];
__device__ __align__(128) __half g_Chi[MROWS * DMODEL];
__device__ __align__(128) __half g_QKVhi[3 * MROWS * DMODEL];  // Q scaled by 0.125*log2e
__device__ __align__(128) __half g_QKVlo[3 * MROWS * DMODEL];  // lo used for K,V only

// ---------------------------------------------------------------------------
// Helpers
// ---------------------------------------------------------------------------
__device__ __forceinline__ uint32_t smem_u32(const void* p) {
    uint32_t a;
    asm("{ .reg .u64 t; cvta.to.shared.u64 t, %1; cvt.u32.u64 %0, t; }" : "=r"(a) : "l"(p));
    return a;
}
__device__ __forceinline__ void ldsm_x4(uint32_t* r, uint32_t addr) {
    asm volatile("ldmatrix.sync.aligned.m8n8.x4.shared.b16 {%0,%1,%2,%3}, [%4];"
                 : "=r"(r[0]), "=r"(r[1]), "=r"(r[2]), "=r"(r[3]) : "r"(addr));
}
__device__ __forceinline__ void ldsm_x4_t(uint32_t* r, uint32_t addr) {
    asm volatile("ldmatrix.sync.aligned.m8n8.x4.trans.shared.b16 {%0,%1,%2,%3}, [%4];"
                 : "=r"(r[0]), "=r"(r[1]), "=r"(r[2]), "=r"(r[3]) : "r"(addr));
}
__device__ __forceinline__ void mma_f16(float* c, const uint32_t* a, uint32_t b0, uint32_t b1) {
    asm volatile(
        "mma.sync.aligned.m16n8k16.row.col.f32.f16.f16.f32 "
        "{%0,%1,%2,%3},{%4,%5,%6,%7},{%8,%9},{%0,%1,%2,%3};"
        : "+f"(c[0]), "+f"(c[1]), "+f"(c[2]), "+f"(c[3])
        : "r"(a[0]), "r"(a[1]), "r"(a[2]), "r"(a[3]), "r"(b0), "r"(b1));
}
__device__ __forceinline__ float ex2f(float x) {
    float r;
    asm("ex2.approx.f32 %0, %1;" : "=f"(r) : "f"(x));
    return r;
}
__device__ __forceinline__ uint32_t pack_h2(float a, float b) {
    __half2 t = __floats2half2_rn(a, b);   // a -> low half
    return *(uint32_t*)&t;
}
// fp16 hi/lo split-pack
__device__ __forceinline__ void split_pack_h(float a, float b, uint32_t& oh, uint32_t& ol) {
    __half ha = __float2half(a), hb = __float2half(b);
    float la = a - __half2float(ha), lb = b - __half2float(hb);
    __half2 th = __halves2half2(ha, hb);
    __half2 tl = __halves2half2(__float2half(la), __float2half(lb));
    oh = *(uint32_t*)&th; ol = *(uint32_t*)&tl;
}
__device__ __forceinline__ uint32_t sw128(uint32_t off) {
    return off ^ ((off >> 3) & 0x70);
}

// ---------------------------------------------------------------------------
// Pre-pass splits (vectorized: 4 floats per thread)
// ---------------------------------------------------------------------------
__global__ void splitx_kernel(const float* __restrict__ src, int n4) {
    int i = blockIdx.x * 256 + threadIdx.x;
    if (i < n4) {
        float4 v = ((const float4*)src)[i];
        uint2 h;
        h.x = pack_h2(v.x, v.y);
        h.y = pack_h2(v.z, v.w);
        ((uint2*)g_Xhi)[i] = h;
    }
}
__global__ void splitwo_kernel(const float* __restrict__ src, int n4) {
    int i = blockIdx.x * 256 + threadIdx.x;
    if (i < n4) {
        float4 v = ((const float4*)src)[i];
        uint2 hh, ll;
        uint32_t h0, l0, h1, l1;
        split_pack_h(v.x, v.y, h0, l0);
        split_pack_h(v.z, v.w, h1, l1);
        hh.x = h0; hh.y = h1;
        ll.x = l0; ll.y = l1;
        ((uint2*)g_Wohi)[i] = hh;
        ((uint2*)g_Wolo)[i] = ll;
    }
}
__global__ void tsplit_kernel(const float* __restrict__ Wq,
                              const float* __restrict__ Wk,
                              const float* __restrict__ Wv) {
    const float* W = (blockIdx.z == 0) ? Wq : (blockIdx.z == 1) ? Wk : Wv;
    __half* Hi = g_Wthi + (size_t)blockIdx.z * DMODEL * DMODEL;
    __half* Lo = g_Wtlo + (size_t)blockIdx.z * DMODEL * DMODEL;
    __shared__ float t[32][33];
    const int k0 = blockIdx.y * 32, n0 = blockIdx.x * 32;
    const int tx = threadIdx.x, ty = threadIdx.y;
#pragma unroll
    for (int r = 0; r < 4; r++)
        t[ty + 8 * r][tx] = W[(size_t)(k0 + ty + 8 * r) * DMODEL + n0 + tx];
    __syncthreads();
#pragma unroll
    for (int r = 0; r < 4; r++) {
        float a = t[tx][ty + 8 * r];
        size_t idx = (size_t)(n0 + ty + 8 * r) * DMODEL + k0 + tx;
        __half h = __float2half(a);
        Hi[idx] = h;
        Lo[idx] = __float2half(a - __half2float(h));
    }
}

// ---------------------------------------------------------------------------
// Tile loaders
// ---------------------------------------------------------------------------
__device__ __forceinline__ void at_load64(uint32_t sdst, const __half* g, int tid) {
#pragma unroll
    for (int t = 0; t < 2; t++) {
        int cid = t * 256 + tid;
        int r = cid >> 3, ch = cid & 7;
        uint32_t off = sw128((uint32_t)(r * 128 + ch * 16));
        const char* src = (const char*)(g + (size_t)r * DMODEL) + ch * 16;
        asm volatile("cp.async.cg.shared.global [%0], [%1], 16;" :: "r"(sdst + off), "l"(src));
    }
}
__device__ __forceinline__ void at_load128(uint32_t sdst, const __half* g, int tid) {
#pragma unroll
    for (int t = 0; t < 4; t++) {
        int cid = t * 256 + tid;
        int r = cid >> 3, ch = cid & 7;
        uint32_t off = sw128((uint32_t)(r * 128 + ch * 16));
        const char* src = (const char*)(g + (size_t)r * DMODEL) + ch * 16;
        asm volatile("cp.async.cg.shared.global [%0], [%1], 16;" :: "r"(sdst + off), "l"(src));
    }
}

// ---------------------------------------------------------------------------
// fp16 2-term mma GEMM: C = A_hi * (B_hi + B_lo)^T. 128x64 tile, 2 CTAs/SM.
// ---------------------------------------------------------------------------
#define GS_STAGE 32768
#define GS_AHI   0
#define GS_BHI   16384
#define GS_BLO   24576
#define GS_TOTAL (2 * GS_STAGE)   // 65536

__global__ __launch_bounds__(256, 2) void gemm_kernel(int mode, float* __restrict__ outp,
                                                      const float* __restrict__ biasp) {
    uint32_t sb = smem_u32(dyn_smem);
    const int tid = threadIdx.x, lane = tid & 31, wid = tid >> 5;
    const int wm = (wid >> 1) * 32;
    const int wn = (wid & 1) * 32;
    const int rowBase = blockIdx.y * 128;
    const int colBase = blockIdx.x * 64;
    const int z = blockIdx.z;
    const int rA = lane & 15, cb16 = (lane >> 4) << 4;

    const __half *Ah, *Bh, *Bl;
    if (mode == 0) {
        Ah = g_Xhi;
        Bh = g_Wthi + (size_t)z * DMODEL * DMODEL;
        Bl = g_Wtlo + (size_t)z * DMODEL * DMODEL;
    } else {
        Ah = g_Chi;
        Bh = g_Wohi; Bl = g_Wolo;
    }
    Ah += (size_t)rowBase * DMODEL;
    Bh += (size_t)colBase * DMODEL;
    Bl += (size_t)colBase * DMODEL;

    uint32_t aOff[2][4], bOff[2][4];
#pragma unroll
    for (int mt = 0; mt < 2; mt++)
#pragma unroll
        for (int ks = 0; ks < 4; ks++)
            aOff[mt][ks] = sw128((uint32_t)((wm + mt * 16 + rA) * 128 + ks * 32 + cb16));
#pragma unroll
    for (int nt = 0; nt < 2; nt++)
#pragma unroll
        for (int ks = 0; ks < 4; ks++)
            bOff[nt][ks] = sw128((uint32_t)((wn + nt * 16 + rA) * 128 + ks * 32 + cb16));

    float c[2][4][4];
#pragma unroll
    for (int i = 0; i < 2; i++)
#pragma unroll
        for (int j = 0; j < 4; j++)
#pragma unroll
            for (int k = 0; k < 4; k++) c[i][j][k] = 0.f;

    at_load128(sb + GS_AHI, Ah, tid);
    at_load64(sb + GS_BHI, Bh, tid);
    at_load64(sb + GS_BLO, Bl, tid);
    asm volatile("cp.async.commit_group;");

    for (int ck = 0; ck < 16; ck++) {
        const int s = ck & 1;
        asm volatile("cp.async.wait_group 0;");
        __syncthreads();

        const uint32_t aHi = sb + (uint32_t)s * GS_STAGE + GS_AHI;
        const uint32_t bHi = sb + (uint32_t)s * GS_STAGE + GS_BHI;
        const uint32_t bLo = sb + (uint32_t)s * GS_STAGE + GS_BLO;

#pragma unroll
        for (int ks = 0; ks < 4; ks++) {
            uint32_t AhF[2][4], BhF[2][4], BlF[2][4];
#pragma unroll
            for (int mt = 0; mt < 2; mt++)
                ldsm_x4(AhF[mt], aHi + aOff[mt][ks]);
#pragma unroll
            for (int nt = 0; nt < 2; nt++) {
                ldsm_x4(BhF[nt], bHi + bOff[nt][ks]);
                ldsm_x4(BlF[nt], bLo + bOff[nt][ks]);
            }
#pragma unroll
            for (int mt = 0; mt < 2; mt++)
#pragma unroll
                for (int nt = 0; nt < 2; nt++)
#pragma unroll
                    for (int o = 0; o < 2; o++) {
                        mma_f16(c[mt][nt * 2 + o], AhF[mt], BhF[nt][o], BhF[nt][o + 2]);
                        mma_f16(c[mt][nt * 2 + o], AhF[mt], BlF[nt][o], BlF[nt][o + 2]);
                    }

            if (ks == 0 && ck + 1 < 16) {
                uint32_t st = sb + (uint32_t)((ck + 1) & 1) * GS_STAGE;
                const int k0 = (ck + 1) * 64;
                at_load128(st + GS_AHI, Ah + k0, tid);
                at_load64(st + GS_BHI, Bh + k0, tid);
                at_load64(st + GS_BLO, Bl + k0, tid);
                asm volatile("cp.async.commit_group;");
            }
        }
    }

    const int cl = 2 * (lane & 3);
    if (mode == 0) {
        const float scale = (z == 0) ? 0.125f * 1.4426950408889634f : 1.0f;
        __half* Hi = g_QKVhi + (size_t)z * MROWS * DMODEL;
        __half* Lo = g_QKVlo + (size_t)z * MROWS * DMODEL;
        const bool needLo = (z != 0);   // lo used only for K and V
#pragma unroll
        for (int mt = 0; mt < 2; mt++) {
            const int r0 = rowBase + wm + mt * 16 + (lane >> 2);
#pragma unroll
            for (int nf = 0; nf < 4; nf++) {
                const int col = colBase + wn + nf * 8 + cl;
                uint32_t h0, l0, h1, l1;
                split_pack_h(c[mt][nf][0] * scale, c[mt][nf][1] * scale, h0, l0);
                split_pack_h(c[mt][nf][2] * scale, c[mt][nf][3] * scale, h1, l1);
                *(uint32_t*)&Hi[(size_t)r0 * DMODEL + col] = h0;
                *(uint32_t*)&Hi[(size_t)(r0 + 8) * DMODEL + col] = h1;
                if (needLo) {
                    *(uint32_t*)&Lo[(size_t)r0 * DMODEL + col] = l0;
                    *(uint32_t*)&Lo[(size_t)(r0 + 8) * DMODEL + col] = l1;
                }
            }
        }
    } else {
#pragma unroll
        for (int mt = 0; mt < 2; mt++) {
            const int r0 = rowBase + wm + mt * 16 + (lane >> 2);
#pragma unroll
            for (int nf = 0; nf < 4; nf++) {
                const int col = colBase + wn + nf * 8 + cl;
                const float b0 = biasp[col], b1 = biasp[col + 1];
                float2 v0 = make_float2(c[mt][nf][0] + b0, c[mt][nf][1] + b1);
                float2 v1 = make_float2(c[mt][nf][2] + b0, c[mt][nf][3] + b1);
                *(float2*)&outp[(size_t)r0 * DMODEL + col] = v0;
                *(float2*)&outp[(size_t)(r0 + 8) * DMODEL + col] = v1;
            }
        }
    }
}

// ---------------------------------------------------------------------------
// fp16 flash attention: S = Qh*(Kh+Kl), O += Ph*(Vh+Vl). exp2 softmax.
// Heavy (large-qt) CTAs scheduled first to shrink the causal tail.
// ---------------------------------------------------------------------------
#define AT_STAGE 32768
#define AT_KHI   0
#define AT_KLO   8192
#define AT_VHI   16384
#define AT_VLO   24576
#define AT_QHI   65536
#define AT_TOTAL 81920

__global__ __launch_bounds__(256, 2) void attn_kernel() {
    uint32_t sb = smem_u32(dyn_smem);
    const int tid = threadIdx.x, lane = tid & 31, wid = tid >> 5;
    const int qt = gridDim.x - 1 - blockIdx.x;   // heavy CTAs first
    const int bh = blockIdx.y;
    const int b = bh >> 4, h = bh & 15;
    const int wm = wid * 16;
    const int rA = lane & 15, cb16 = (lane >> 4) << 4;
    const int jmax = 2 * qt + 1;

    const size_t qoff = ((size_t)b * S_LEN + qt * 128) * DMODEL + h * HDIM;
    const __half* Qh_g = g_QKVhi + qoff;
    const size_t kvbase = (size_t)b * S_LEN * DMODEL + h * HDIM;
    const __half* Kh_g = g_QKVhi + (size_t)MROWS * DMODEL + kvbase;
    const __half* Kl_g = g_QKVlo + (size_t)MROWS * DMODEL + kvbase;
    const __half* Vh_g = g_QKVhi + (size_t)2 * MROWS * DMODEL + kvbase;
    const __half* Vl_g = g_QKVlo + (size_t)2 * MROWS * DMODEL + kvbase;

    at_load128(sb + AT_QHI, Qh_g, tid);
    at_load64(sb + AT_KHI, Kh_g, tid);
    at_load64(sb + AT_KLO, Kl_g, tid);
    at_load64(sb + AT_VHI, Vh_g, tid);
    at_load64(sb + AT_VLO, Vl_g, tid);
    asm volatile("cp.async.commit_group;");

    float co[8][4];
#pragma unroll
    for (int i = 0; i < 8; i++)
#pragma unroll
        for (int j = 0; j < 4; j++) co[i][j] = 0.f;
    float m_i[2] = {-INFINITY, -INFINITY};
    float l_i[2] = {0.f, 0.f};
    uint32_t QhF[4][4];

    for (int j = 0; j <= jmax; j++) {
        asm volatile("cp.async.wait_group 0;");
        __syncthreads();

        if (j + 1 <= jmax) {
            uint32_t stn = sb + (uint32_t)((j + 1) & 1) * AT_STAGE;
            const size_t ro = (size_t)(j + 1) * 64 * DMODEL;
            at_load64(stn + AT_KHI, Kh_g + ro, tid);
            at_load64(stn + AT_KLO, Kl_g + ro, tid);
            at_load64(stn + AT_VHI, Vh_g + ro, tid);
            at_load64(stn + AT_VLO, Vl_g + ro, tid);
            asm volatile("cp.async.commit_group;");
        }

        if (j == 0) {
#pragma unroll
            for (int ks = 0; ks < 4; ks++) {
                uint32_t off = sw128((uint32_t)((wm + rA) * 128 + ks * 32 + cb16));
                ldsm_x4(QhF[ks], sb + AT_QHI + off);
            }
        }

        const int qmin = qt * 128 + wm;
        if (j * 64 > qmin + 15) continue;

        const uint32_t st = sb + (uint32_t)(j & 1) * AT_STAGE;

        // ---- S = Qh (Kh + Kl)^T ----
        float cs[8][4];
#pragma unroll
        for (int i = 0; i < 8; i++)
#pragma unroll
            for (int e = 0; e < 4; e++) cs[i][e] = 0.f;
#pragma unroll
        for (int ks = 0; ks < 4; ks++) {
#pragma unroll
            for (int nt = 0; nt < 4; nt++) {
                uint32_t kh[4], kl[4];
                uint32_t off = sw128((uint32_t)((nt * 16 + rA) * 128 + ks * 32 + cb16));
                ldsm_x4(kh, st + AT_KHI + off);
                ldsm_x4(kl, st + AT_KLO + off);
#pragma unroll
                for (int o = 0; o < 2; o++) {
                    mma_f16(cs[nt * 2 + o], QhF[ks], kh[o], kh[o + 2]);
                    mma_f16(cs[nt * 2 + o], QhF[ks], kl[o], kl[o + 2]);
                }
            }
        }

        if (j * 64 + 63 > qmin) {
            const int r0 = lane >> 2, c0 = 2 * (lane & 3);
#pragma unroll
            for (int nf = 0; nf < 8; nf++) {
#pragma unroll
                for (int e = 0; e < 4; e++) {
                    const int col = nf * 8 + c0 + (e & 1);
                    const int row = r0 + ((e >> 1) * 8);
                    if (j * 64 + col > qmin + row) cs[nf][e] = -1e30f;
                }
            }
        }

        // ---- online softmax (exp2 domain) ----
        float mx0 = -INFINITY, mx1 = -INFINITY;
#pragma unroll
        for (int nf = 0; nf < 8; nf++) {
            mx0 = fmaxf(mx0, fmaxf(cs[nf][0], cs[nf][1]));
            mx1 = fmaxf(mx1, fmaxf(cs[nf][2], cs[nf][3]));
        }
        mx0 = fmaxf(mx0, __shfl_xor_sync(0xffffffffu, mx0, 1));
        mx0 = fmaxf(mx0, __shfl_xor_sync(0xffffffffu, mx0, 2));
        mx1 = fmaxf(mx1, __shfl_xor_sync(0xffffffffu, mx1, 1));
        mx1 = fmaxf(mx1, __shfl_xor_sync(0xffffffffu, mx1, 2));
        const float mn0 = fmaxf(m_i[0], mx0), mn1 = fmaxf(m_i[1], mx1);
        const float corr0 = ex2f(m_i[0] - mn0), corr1 = ex2f(m_i[1] - mn1);
        float rs0 = 0.f, rs1 = 0.f;
#pragma unroll
        for (int nf = 0; nf < 8; nf++) {
            cs[nf][0] = ex2f(cs[nf][0] - mn0); rs0 += cs[nf][0];
            cs[nf][1] = ex2f(cs[nf][1] - mn0); rs0 += cs[nf][1];
            cs[nf][2] = ex2f(cs[nf][2] - mn1); rs1 += cs[nf][2];
            cs[nf][3] = ex2f(cs[nf][3] - mn1); rs1 += cs[nf][3];
        }
        rs0 += __shfl_xor_sync(0xffffffffu, rs0, 1);
        rs0 += __shfl_xor_sync(0xffffffffu, rs0, 2);
        rs1 += __shfl_xor_sync(0xffffffffu, rs1, 1);
        rs1 += __shfl_xor_sync(0xffffffffu, rs1, 2);
        l_i[0] = l_i[0] * corr0 + rs0; m_i[0] = mn0;
        l_i[1] = l_i[1] * corr1 + rs1; m_i[1] = mn1;
#pragma unroll
        for (int nf = 0; nf < 8; nf++) {
            co[nf][0] *= corr0; co[nf][1] *= corr0;
            co[nf][2] *= corr1; co[nf][3] *= corr1;
        }

        // ---- O += Ph (Vh + Vl) ----
#pragma unroll
        for (int kt = 0; kt < 4; kt++) {
            uint32_t pah[4];
            pah[0] = pack_h2(cs[2 * kt][0],     cs[2 * kt][1]);
            pah[1] = pack_h2(cs[2 * kt][2],     cs[2 * kt][3]);
            pah[2] = pack_h2(cs[2 * kt + 1][0], cs[2 * kt + 1][1]);
            pah[3] = pack_h2(cs[2 * kt + 1][2], cs[2 * kt + 1][3]);
#pragma unroll
            for (int nt = 0; nt < 4; nt++) {
                uint32_t vh[4], vl[4];
                uint32_t off = sw128((uint32_t)((kt * 16 + rA) * 128 + nt * 32 + cb16));
                ldsm_x4_t(vh, st + AT_VHI + off);
                ldsm_x4_t(vl, st + AT_VLO + off);
                mma_f16(co[nt * 2 + 0], pah, vh[0], vh[1]);
                mma_f16(co[nt * 2 + 0], pah, vl[0], vl[1]);
                mma_f16(co[nt * 2 + 1], pah, vh[2], vh[3]);
                mma_f16(co[nt * 2 + 1], pah, vl[2], vl[3]);
            }
        }
    }

    // ---- epilogue: ctx -> fp16 hi (only) ----
    const float inv0 = 1.f / l_i[0], inv1 = 1.f / l_i[1];
    const int row0 = b * S_LEN + qt * 128 + wm + (lane >> 2);
    const int colb = h * HDIM + 2 * (lane & 3);
#pragma unroll
    for (int nf = 0; nf < 8; nf++) {
        const int col = colb + nf * 8;
        *(uint32_t*)&g_Chi[(size_t)row0 * DMODEL + col] =
            pack_h2(co[nf][0] * inv0, co[nf][1] * inv0);
        *(uint32_t*)&g_Chi[(size_t)(row0 + 8) * DMODEL + col] =
            pack_h2(co[nf][2] * inv1, co[nf][3] * inv1);
    }
}

// ---------------------------------------------------------------------------
extern "C" void kernel_launch(void* const* d_in, const int* in_sizes, int n_in,
                              void* d_out, int out_size)
{
    const float* x  = (const float*)d_in[0];
    const float* Wq = (const float*)d_in[1];
    const float* Wk = (const float*)d_in[2];
    const float* Wv = (const float*)d_in[3];
    const float* Wo = (const float*)d_in[4];
    const float* bo = (const float*)d_in[5];
    float* out = (float*)d_out;

    cudaFuncSetAttribute(gemm_kernel, cudaFuncAttributeMaxDynamicSharedMemorySize, GS_TOTAL);
    cudaFuncSetAttribute(attn_kernel, cudaFuncAttributeMaxDynamicSharedMemorySize, AT_TOTAL);

    splitx_kernel<<<(MROWS * DMODEL / 4 + 255) / 256, 256>>>(x, MROWS * DMODEL / 4);
    splitwo_kernel<<<(DMODEL * DMODEL / 4 + 255) / 256, 256>>>(Wo, DMODEL * DMODEL / 4);
    tsplit_kernel<<<dim3(32, 32, 3), dim3(32, 8)>>>(Wq, Wk, Wv);

    gemm_kernel<<<dim3(DMODEL / 64, MROWS / 128, 3), 256, GS_TOTAL>>>(0, nullptr, nullptr);

    attn_kernel<<<dim3(S_LEN / 128, BATCH * NHEADS), 256, AT_TOTAL>>>();

    gemm_kernel<<<dim3(DMODEL / 64, MROWS / 128, 1), 256, GS_TOTAL>>>(1, out, bo);
}